// round 1
// baseline (speedup 1.0000x reference)
#include <cuda_runtime.h>
#include <math.h>

#define BB 8
#define DD 128
#define NN 16384
#define KK 512
#define KT 4

// scratch (device globals — no allocation allowed)
__device__ float g_tgt_global[BB * DD];
__device__ float g_scalar[BB];
__device__ float g_R[BB * NN];   // exp(-logits[b,n])

// ---------------------------------------------------------------------------
// Kernel 1: tgt_global[b,d] = max_n tgt_embedding[b,d,n]
// ---------------------------------------------------------------------------
__global__ void __launch_bounds__(256) k_rowmax(const float* __restrict__ tgt) {
    const int row = blockIdx.x;  // b*DD + d
    const float4* p4 = (const float4*)(tgt + (size_t)row * NN);
    float m = -INFINITY;
    for (int i = threadIdx.x; i < NN / 4; i += 256) {
        float4 v = p4[i];
        m = fmaxf(m, fmaxf(fmaxf(v.x, v.y), fmaxf(v.z, v.w)));
    }
    #pragma unroll
    for (int o = 16; o; o >>= 1) m = fmaxf(m, __shfl_xor_sync(0xffffffffu, m, o));
    __shared__ float sm[8];
    if ((threadIdx.x & 31) == 0) sm[threadIdx.x >> 5] = m;
    __syncthreads();
    if (threadIdx.x == 0) {
        float r = sm[0];
        #pragma unroll
        for (int i = 1; i < 8; i++) r = fmaxf(r, sm[i]);
        g_tgt_global[row] = r;
    }
}

// ---------------------------------------------------------------------------
// Kernel 2: g_scalar[b] = sum_d tgt_global[b,d] * conv_w[DD+d]
// ---------------------------------------------------------------------------
__global__ void __launch_bounds__(128) k_scalar(const float* __restrict__ conv_w) {
    const int b = blockIdx.x;
    float v = g_tgt_global[b * DD + threadIdx.x] * conv_w[DD + threadIdx.x];
    #pragma unroll
    for (int o = 16; o; o >>= 1) v += __shfl_xor_sync(0xffffffffu, v, o);
    __shared__ float sm[4];
    if ((threadIdx.x & 31) == 0) sm[threadIdx.x >> 5] = v;
    __syncthreads();
    if (threadIdx.x == 0) g_scalar[b] = (sm[0] + sm[1]) + (sm[2] + sm[3]);
}

// ---------------------------------------------------------------------------
// Kernel 3: g_R[b,n] = exp(-(dot(src[b,:,n], w_src) + scalar[b]))
// ---------------------------------------------------------------------------
__global__ void __launch_bounds__(256) k_logits(const float* __restrict__ src,
                                                const float* __restrict__ conv_w) {
    __shared__ float ws[DD];
    const int b = blockIdx.y;
    const int n = blockIdx.x * 256 + threadIdx.x;
    if (threadIdx.x < DD) ws[threadIdx.x] = conv_w[threadIdx.x];
    __syncthreads();
    const float* srcb = src + (size_t)b * DD * NN;
    float acc = 0.0f;
    #pragma unroll 16
    for (int d = 0; d < DD; ++d)
        acc = fmaf(__ldg(srcb + (size_t)d * NN + n), ws[d], acc);
    g_R[b * NN + n] = expf(-(acc + g_scalar[b]));
}

// ---------------------------------------------------------------------------
// fast ln(u), u in [1e-10, 1], pure FMA/ALU (no MUFU), ~1e-7 rel accuracy.
// Cephes logf polynomial after reduction to m in [sqrt(0.5), sqrt(2)).
// ---------------------------------------------------------------------------
__device__ __forceinline__ float fast_ln(float u) {
    unsigned int ui = __float_as_uint(u);
    int k = ((int)(ui - 0x3F3504F3u)) >> 23;                 // arithmetic shift
    float m = __uint_as_float(ui - ((unsigned int)k << 23)); // [0.7071, 1.4142)
    float f = m - 1.0f;                                      // exact
    float z = f * f;
    float p =              7.0376836292e-2f;
    p = fmaf(p, f, -1.1514610310e-1f);
    p = fmaf(p, f,  1.1676998740e-1f);
    p = fmaf(p, f, -1.2420140846e-1f);
    p = fmaf(p, f,  1.4249322787e-1f);
    p = fmaf(p, f, -1.6668057665e-1f);
    p = fmaf(p, f,  2.0000714765e-1f);
    p = fmaf(p, f, -2.4999993993e-1f);
    p = fmaf(p, f,  3.3333331174e-1f);
    float lnm = fmaf(f * p, z, fmaf(-0.5f, z, f));           // ln(m)
    float kf = (float)k;
    // ln2 split for accuracy at large |k|
    return fmaf(kf, 0.693145751953125f, fmaf(kf, 1.42860677e-6f, lnm));
}

// ---------------------------------------------------------------------------
// Kernel 4: per (b,k): idx = argmin_n (-ln u[b,k,n]) * R[b,n]   (== argmax z)
// then gather points / src_embedding columns into the outputs.
// Block = 256 threads, handles KT=4 consecutive k for one b (reuses R).
// ---------------------------------------------------------------------------
__global__ void __launch_bounds__(256) k_argmin_gather(
    const float* __restrict__ gumbel, const float* __restrict__ points,
    const float* __restrict__ src, const float* __restrict__ temperature,
    float* __restrict__ out)
{
    const int b   = blockIdx.y;
    const int k0  = blockIdx.x * KT;
    const int tid = threadIdx.x;
    const bool flip = temperature[b] < 0.0f;  // tau<0: argmax of v instead

    const float4* R4 = (const float4*)(g_R + (size_t)b * NN);
    const float4* U4[KT];
    #pragma unroll
    for (int kk = 0; kk < KT; ++kk)
        U4[kk] = (const float4*)(gumbel + ((size_t)(b * KK + k0 + kk)) * NN);

    unsigned long long best[KT];
    #pragma unroll
    for (int kk = 0; kk < KT; ++kk) best[kk] = ~0ull;

    for (int j = tid; j < NN / 4; j += 256) {
        float4 r4 = R4[j];
        float rr[4] = {r4.x, r4.y, r4.z, r4.w};
        #pragma unroll
        for (int kk = 0; kk < KT; ++kk) {
            float4 u4 = U4[kk][j];
            float uu[4] = {u4.x, u4.y, u4.z, u4.w};
            #pragma unroll
            for (int l = 0; l < 4; ++l) {
                // reference clip: [1e-10, fp32(1-1e-10)==1.0]
                float uc = fminf(fmaxf(uu[l], 1e-10f), 1.0f);
                float w  = fast_ln(uc);              // ln(u) <= 0
                float v  = (-w) * rr[l];             // > 0 ; smaller v <=> larger z
                unsigned int vb = __float_as_uint(v);
                if (flip) vb = ~vb;
                unsigned long long key =
                    ((unsigned long long)vb << 32) | (unsigned int)(j * 4 + l);
                best[kk] = (key < best[kk]) ? key : best[kk];
            }
        }
    }

    // block-wide min-reduce per kk (tie -> smaller n, matching jnp.argmax)
    __shared__ unsigned long long s_red[8][KT];
    __shared__ int s_idx[KT];
    const int lane = tid & 31, warp = tid >> 5;
    #pragma unroll
    for (int kk = 0; kk < KT; ++kk) {
        unsigned long long key = best[kk];
        #pragma unroll
        for (int o = 16; o; o >>= 1) {
            unsigned long long oth = __shfl_xor_sync(0xffffffffu, key, o);
            key = (oth < key) ? oth : key;
        }
        if (lane == 0) s_red[warp][kk] = key;
    }
    __syncthreads();
    if (tid < KT) {
        unsigned long long key = s_red[0][tid];
        #pragma unroll
        for (int w2 = 1; w2 < 8; ++w2) {
            unsigned long long oth = s_red[w2][tid];
            key = (oth < key) ? oth : key;
        }
        s_idx[tid] = (int)(key & 0xFFFFFFFFull);
    }
    __syncthreads();

    // gather: scores are exactly one-hot value-wise (|s-1| <= 2^-24)
    for (int item = tid; item < KT * (DD + 3); item += 256) {
        const int kk  = item / (DD + 3);
        const int c   = item - kk * (DD + 3);
        const int idx = s_idx[kk];
        const int kq  = k0 + kk;
        if (c < 3) {
            out[((size_t)b * 3 + c) * KK + kq] = points[((size_t)b * 3 + c) * NN + idx];
        } else {
            const int d = c - 3;
            out[(size_t)BB * 3 * KK + ((size_t)b * DD + d) * KK + kq] =
                src[((size_t)b * DD + d) * NN + idx];
        }
    }
}

// ---------------------------------------------------------------------------
extern "C" void kernel_launch(void* const* d_in, const int* in_sizes, int n_in,
                              void* d_out, int out_size) {
    const float* points = (const float*)d_in[0];
    const float* src    = (const float*)d_in[1];
    const float* tgt    = (const float*)d_in[2];
    const float* temp   = (const float*)d_in[3];
    const float* conv_w = (const float*)d_in[4];
    const float* gumbel = (const float*)d_in[5];
    float* out = (float*)d_out;

    k_rowmax<<<BB * DD, 256>>>(tgt);
    k_scalar<<<BB, 128>>>(conv_w);
    k_logits<<<dim3(NN / 256, BB), 256>>>(src, conv_w);
    k_argmin_gather<<<dim3(KK / KT, BB), 256>>>(gumbel, points, src, temp, out);
}